// round 1
// baseline (speedup 1.0000x reference)
#include <cuda_runtime.h>
#include <math.h>

#define B_   2
#define T_   1024
#define D_   768
#define H_   12
#define L_   4
#define E_   8
#define DFF_ 3072
#define V_   32000
#define HEAD_ 64
#define BT_  (B_ * T_)      // 2048
#define TD3_ (3 * D_)       // 2304

// ---------------- scratch (device globals; no allocation) ----------------
__device__ float g_x  [BT_ * D_];                  // residual stream
__device__ float g_h  [BT_ * D_];                  // ln output
__device__ float g_qkv[BT_ * TD3_];                // qkv projection
__device__ float g_sc [(size_t)B_ * H_ * T_ * T_]; // attention scores (100MB)
__device__ float g_ao [BT_ * D_];                  // attention concat output
__device__ float g_hid[BT_ * DFF_];                // expert hidden
__device__ float g_w  [BT_ * E_];                  // routing weights

// ---------------- embedding ----------------
__global__ void embed_kernel(const int* __restrict__ tokens,
                             const float* __restrict__ wte,
                             const float* __restrict__ wpe,
                             float* __restrict__ x) {
    int r = blockIdx.x;            // 0..2047
    int t = r & (T_ - 1);
    int tok = tokens[r];
    const float* we = wte + (size_t)tok * D_;
    const float* pe = wpe + (size_t)t * D_;
    float* xr = x + (size_t)r * D_;
    for (int i = threadIdx.x; i < D_; i += 256) xr[i] = we[i] + pe[i];
}

// ---------------- layernorm (row of 768, block=256) ----------------
__global__ void ln_kernel(const float* __restrict__ in,
                          const float* __restrict__ g,
                          const float* __restrict__ b,
                          float* __restrict__ out) {
    int r = blockIdx.x, tid = threadIdx.x;
    const float* xr = in + (size_t)r * D_;
    float v[3], s = 0.f, ss = 0.f;
#pragma unroll
    for (int n = 0; n < 3; n++) {
        float t = xr[tid + n * 256];
        v[n] = t; s += t; ss += t * t;
    }
    __shared__ float r1[256], r2[256];
    r1[tid] = s; r2[tid] = ss;
    __syncthreads();
    for (int o = 128; o > 0; o >>= 1) {
        if (tid < o) { r1[tid] += r1[tid + o]; r2[tid] += r2[tid + o]; }
        __syncthreads();
    }
    float mu = r1[0] * (1.f / D_);
    float var = r2[0] * (1.f / D_) - mu * mu;
    float rstd = rsqrtf(var + 1e-5f);
    float* orow = out + (size_t)r * D_;
#pragma unroll
    for (int n = 0; n < 3; n++) {
        int i = tid + n * 256;
        orow[i] = (v[n] - mu) * rstd * g[i] + b[i];
    }
}

// ---------------- generic NT SGEMM: C[M,N] = A[M,K] * B[N,K]^T ----------------
// MODE 0: store   1: relu-store   2: C += acc (residual)   3: C += rs[m*stride]*acc
template <int MODE>
__global__ void __launch_bounds__(256) gemm_nt(
    const float* __restrict__ A, const float* __restrict__ B,
    float* __restrict__ C, int M, int N, int K,
    const float* __restrict__ rs, int rs_stride) {
    __shared__ float As[8][128];
    __shared__ float Bs[8][128];
    int tid = threadIdx.x;
    int m0 = blockIdx.y * 128, n0 = blockIdx.x * 128;
    int arow = tid >> 1, acol = (tid & 1) * 4;
    const float* Ap = A + (size_t)(m0 + arow) * K + acol;
    const float* Bp = B + (size_t)(n0 + arow) * K + acol;
    int ty = tid >> 4, tx = tid & 15;
    float acc[8][8] = {};
    for (int k0 = 0; k0 < K; k0 += 8) {
        float4 av = *(const float4*)(Ap + k0);
        float4 bv = *(const float4*)(Bp + k0);
        __syncthreads();
        As[acol + 0][arow] = av.x; As[acol + 1][arow] = av.y;
        As[acol + 2][arow] = av.z; As[acol + 3][arow] = av.w;
        Bs[acol + 0][arow] = bv.x; Bs[acol + 1][arow] = bv.y;
        Bs[acol + 2][arow] = bv.z; Bs[acol + 3][arow] = bv.w;
        __syncthreads();
#pragma unroll
        for (int k = 0; k < 8; k++) {
            float a[8], b[8];
            *(float4*)(a)     = *(const float4*)&As[k][ty * 8];
            *(float4*)(a + 4) = *(const float4*)&As[k][ty * 8 + 4];
            *(float4*)(b)     = *(const float4*)&Bs[k][tx * 8];
            *(float4*)(b + 4) = *(const float4*)&Bs[k][tx * 8 + 4];
#pragma unroll
            for (int i = 0; i < 8; i++)
#pragma unroll
                for (int j = 0; j < 8; j++) acc[i][j] += a[i] * b[j];
        }
    }
#pragma unroll
    for (int i = 0; i < 8; i++) {
        int m = m0 + ty * 8 + i;
        float s = (MODE == 3) ? rs[(size_t)m * rs_stride] : 0.f;
        float* crow = C + (size_t)m * N + n0 + tx * 8;
#pragma unroll
        for (int j = 0; j < 8; j++) {
            if (MODE == 0)      crow[j] = acc[i][j];
            else if (MODE == 1) crow[j] = fmaxf(acc[i][j], 0.f);
            else if (MODE == 2) crow[j] += acc[i][j];
            else                crow[j] += s * acc[i][j];
        }
    }
}

// ---------------- attention: S = Q K^T * scale, causal (lower tiles only) ----------------
__global__ void __launch_bounds__(256) attn_scores(const float* __restrict__ qkv,
                                                   float* __restrict__ sc) {
    int kt = blockIdx.x, qt = blockIdx.y, bh = blockIdx.z;
    if (kt > qt) return;   // strictly-upper tiles never read downstream
    int b = bh / H_, h = bh - b * H_;
    const float* Qb = qkv + (size_t)b * T_ * TD3_ + h * HEAD_;
    const float* Kb = Qb + D_;
    __shared__ float As[16][65], Bs[16][65];
    int tid = threadIdx.x;
    int m = tid >> 2, k4 = (tid & 3) * 4;
    int ty = tid >> 4, tx = tid & 15;
    float acc[4][4] = {};
    for (int k0 = 0; k0 < HEAD_; k0 += 16) {
        float4 a  = *(const float4*)(Qb + (size_t)(qt * 64 + m) * TD3_ + k0 + k4);
        float4 bb = *(const float4*)(Kb + (size_t)(kt * 64 + m) * TD3_ + k0 + k4);
        __syncthreads();
        As[k4 + 0][m] = a.x;  As[k4 + 1][m] = a.y;  As[k4 + 2][m] = a.z;  As[k4 + 3][m] = a.w;
        Bs[k4 + 0][m] = bb.x; Bs[k4 + 1][m] = bb.y; Bs[k4 + 2][m] = bb.z; Bs[k4 + 3][m] = bb.w;
        __syncthreads();
#pragma unroll
        for (int k = 0; k < 16; k++) {
            float av[4], bv[4];
#pragma unroll
            for (int i = 0; i < 4; i++) av[i] = As[k][ty * 4 + i];
#pragma unroll
            for (int j = 0; j < 4; j++) bv[j] = Bs[k][tx * 4 + j];
#pragma unroll
            for (int i = 0; i < 4; i++)
#pragma unroll
                for (int j = 0; j < 4; j++) acc[i][j] += av[i] * bv[j];
        }
    }
    float* out = sc + ((size_t)bh << 20);
#pragma unroll
    for (int i = 0; i < 4; i++) {
        int q = qt * 64 + ty * 4 + i;
#pragma unroll
        for (int j = 0; j < 4; j++) {
            int kk = kt * 64 + tx * 4 + j;
            float v = acc[i][j] * 0.125f;       // 1/sqrt(64)
            if (kk > q) v = -1e30f;
            out[(size_t)q * T_ + kk] = v;
        }
    }
}

// ---------------- row softmax over [0, kend) only ----------------
__global__ void softmax_rows(float* __restrict__ sc) {
    int q = blockIdx.x, bh = blockIdx.y, tid = threadIdx.x;
    float* row = sc + ((size_t)bh << 20) + (size_t)q * T_;
    int kend = ((q >> 6) + 1) << 6;  // end of diagonal tile
    float lmax = -3e38f;
    for (int i = tid; i < kend; i += 256) lmax = fmaxf(lmax, row[i]);
    __shared__ float red[256];
    red[tid] = lmax; __syncthreads();
    for (int o = 128; o > 0; o >>= 1) {
        if (tid < o) red[tid] = fmaxf(red[tid], red[tid + o]);
        __syncthreads();
    }
    float m = red[0];
    __syncthreads();
    float v[4]; int n = 0; float lsum = 0.f;
    for (int i = tid; i < kend; i += 256) {
        float e = __expf(row[i] - m);
        v[n++] = e; lsum += e;
    }
    red[tid] = lsum; __syncthreads();
    for (int o = 128; o > 0; o >>= 1) {
        if (tid < o) red[tid] += red[tid + o];
        __syncthreads();
    }
    float inv = 1.f / red[0];
    n = 0;
    for (int i = tid; i < kend; i += 256) row[i] = v[n++] * inv;
}

// ---------------- attention: O = P V, K-loop bounded at diagonal ----------------
__global__ void __launch_bounds__(256) attn_out(const float* __restrict__ sc,
                                                const float* __restrict__ qkv,
                                                float* __restrict__ ao) {
    int qt = blockIdx.x, bh = blockIdx.y;
    int b = bh / H_, h = bh - b * H_;
    const float* P = sc + ((size_t)bh << 20) + (size_t)qt * 64 * T_;
    const float* V = qkv + (size_t)b * T_ * TD3_ + 2 * D_ + h * HEAD_;
    __shared__ float Ps[64][20];
    __shared__ float Vs[16][64];
    int tid = threadIdx.x;
    int m = tid >> 2, k4 = (tid & 3) * 4;     // P loads
    int kv = tid >> 4, j4 = (tid & 15) * 4;   // V loads
    int ty = tid >> 4, tx = tid & 15;
    float acc[4][4] = {};
    int kmax = (qt + 1) * 64;
    for (int k0 = 0; k0 < kmax; k0 += 16) {
        float4 p  = *(const float4*)(P + (size_t)m * T_ + k0 + k4);
        float4 vv = *(const float4*)(V + (size_t)(k0 + kv) * TD3_ + j4);
        __syncthreads();
        *(float4*)&Ps[m][k4] = p;
        *(float4*)&Vs[kv][j4] = vv;
        __syncthreads();
#pragma unroll
        for (int k = 0; k < 16; k++) {
            float pv[4], vb[4];
#pragma unroll
            for (int i = 0; i < 4; i++) pv[i] = Ps[ty * 4 + i][k];
            *(float4*)vb = *(const float4*)&Vs[k][tx * 4];
#pragma unroll
            for (int i = 0; i < 4; i++)
#pragma unroll
                for (int j = 0; j < 4; j++) acc[i][j] += pv[i] * vb[j];
        }
    }
    float* O = ao + (size_t)(b * T_ + qt * 64) * D_ + h * HEAD_;
#pragma unroll
    for (int i = 0; i < 4; i++)
#pragma unroll
        for (int j = 0; j < 4; j++)
            O[(size_t)(ty * 4 + i) * D_ + tx * 4 + j] = acc[i][j];
}

// ---------------- router: dots + softmax + top2 + renorm, one block/token ----------------
__global__ void router_kernel(const float* __restrict__ h,
                              const float* __restrict__ rw,
                              float* __restrict__ w) {
    int r = blockIdx.x;
    int warp = threadIdx.x >> 5, lane = threadIdx.x & 31;
    const float* hr = h + (size_t)r * D_;
    const float* we = rw + (size_t)warp * D_;
    float dot = 0.f;
    for (int i = lane; i < D_; i += 32) dot += hr[i] * we[i];
    for (int o = 16; o > 0; o >>= 1) dot += __shfl_xor_sync(0xffffffffu, dot, o);
    __shared__ float s[E_];
    if (lane == 0) s[warp] = dot;
    __syncthreads();
    if (threadIdx.x == 0) {
        float mx = s[0];
        for (int e = 1; e < E_; e++) mx = fmaxf(mx, s[e]);
        float p[E_], sum = 0.f;
        for (int e = 0; e < E_; e++) { p[e] = __expf(s[e] - mx); sum += p[e]; }
        float inv = 1.f / sum;
        for (int e = 0; e < E_; e++) p[e] *= inv;
        int i1 = 0;
        for (int e = 1; e < E_; e++) if (s[e] > s[i1]) i1 = e;
        int i2 = (i1 == 0) ? 1 : 0;
        for (int e = 0; e < E_; e++) if (e != i1 && s[e] > s[i2]) i2 = e;
        float denom = p[i1] + p[i2] + 1e-8f;
        for (int e = 0; e < E_; e++)
            w[(size_t)r * E_ + e] = (e == i1 || e == i2) ? p[e] / denom : 0.f;
    }
}

// ---------------- launch ----------------
extern "C" void kernel_launch(void* const* d_in, const int* in_sizes, int n_in,
                              void* d_out, int out_size) {
    (void)in_sizes; (void)n_in; (void)out_size;
    const int*   tokens   = (const int*)  d_in[0];
    const float* wte      = (const float*)d_in[1];
    const float* wpe      = (const float*)d_in[2];
    const float* norm0_g  = (const float*)d_in[3];
    const float* norm0_b  = (const float*)d_in[4];
    const float* norm1_g  = (const float*)d_in[5];
    const float* norm1_b  = (const float*)d_in[6];
    const float* norm2_g  = (const float*)d_in[7];
    const float* norm2_b  = (const float*)d_in[8];
    const float* qkv_w    = (const float*)d_in[9];
    const float* proj_w   = (const float*)d_in[10];
    const float* router_w = (const float*)d_in[11];
    const float* fc1      = (const float*)d_in[12];
    const float* fc2      = (const float*)d_in[13];
    const float* lm_head  = (const float*)d_in[14];
    float* out = (float*)d_out;

    float *x, *h, *qkv, *sc, *ao, *hid, *w;
    cudaGetSymbolAddress((void**)&x,   g_x);
    cudaGetSymbolAddress((void**)&h,   g_h);
    cudaGetSymbolAddress((void**)&qkv, g_qkv);
    cudaGetSymbolAddress((void**)&sc,  g_sc);
    cudaGetSymbolAddress((void**)&ao,  g_ao);
    cudaGetSymbolAddress((void**)&hid, g_hid);
    cudaGetSymbolAddress((void**)&w,   g_w);

    embed_kernel<<<BT_, 256>>>(tokens, wte, wpe, x);
    ln_kernel<<<BT_, 256>>>(x, norm0_g, norm0_b, x);

    for (int l = 0; l < L_; l++) {
        // --- attention block ---
        ln_kernel<<<BT_, 256>>>(x, norm1_g + l * D_, norm1_b + l * D_, h);
        {
            dim3 g(TD3_ / 128, BT_ / 128);
            gemm_nt<0><<<g, 256>>>(h, qkv_w + (size_t)l * TD3_ * D_, qkv,
                                   BT_, TD3_, D_, nullptr, 0);
        }
        {
            dim3 g(T_ / 64, T_ / 64, B_ * H_);
            attn_scores<<<g, 256>>>(qkv, sc);
        }
        {
            dim3 g(T_, B_ * H_);
            softmax_rows<<<g, 256>>>(sc);
        }
        {
            dim3 g(T_ / 64, B_ * H_);
            attn_out<<<g, 256>>>(sc, qkv, ao);
        }
        {
            dim3 g(D_ / 128, BT_ / 128);
            gemm_nt<2><<<g, 256>>>(ao, proj_w + (size_t)l * D_ * D_, x,
                                   BT_, D_, D_, nullptr, 0);  // x += attn proj
        }
        // --- MoE block ---
        ln_kernel<<<BT_, 256>>>(x, norm2_g + l * D_, norm2_b + l * D_, h);
        router_kernel<<<BT_, 256>>>(h, router_w + (size_t)l * E_ * D_, w);
        for (int e = 0; e < E_; e++) {
            dim3 g1(DFF_ / 128, BT_ / 128);
            gemm_nt<1><<<g1, 256>>>(h, fc1 + ((size_t)(l * E_ + e)) * DFF_ * D_,
                                    hid, BT_, DFF_, D_, nullptr, 0);
            dim3 g2(D_ / 128, BT_ / 128);
            gemm_nt<3><<<g2, 256>>>(hid, fc2 + ((size_t)(l * E_ + e)) * D_ * DFF_,
                                    x, BT_, D_, DFF_, w + e, E_);  // x += w_e * eo
        }
    }
    {
        dim3 g(V_ / 128, BT_ / 128);
        gemm_nt<0><<<g, 256>>>(x, lm_head, out, BT_, V_, D_, nullptr, 0);
    }
}